// round 1
// baseline (speedup 1.0000x reference)
#include <cuda_runtime.h>
#include <cuda_bf16.h>
#include <cstdint>

// Problem shape (fixed by the dataset): N=M=4096, DIM=8, TASKS=8
constexpr int NN   = 4096;
constexpr int MM   = 4096;
constexpr int DIMC = 8;
constexpr int TT   = 8;

constexpr int TR = 32;    // rows per group (== warp size)
constexpr int TC = 128;   // columns per tile
constexpr int TILE_STRIDE = 132;            // padded smem stride (conflict-free)
constexpr int MAXG = 136;                   // >= floor(4096/32) + (TASKS-1) = 135

// Scratch (no cudaMalloc allowed)
__device__ int g_perm[MAXG * TR];   // row indices grouped by task, -1 = pad
__device__ int g_gtask[MAXG];       // task id per group, -1 = unused group

__device__ __forceinline__ float softplus_f(float a) {
    // softplus(a) = log(1 + e^a); stable for large a
    return (a > 20.0f) ? a : log1pf(__expf(a));
}

// ---------------------------------------------------------------------------
// Prep: counting-sort rows by task into 32-row groups (single CTA).
// Order within a task is nondeterministic (atomic) but output is invariant:
// each row is computed independently and written exactly once.
// ---------------------------------------------------------------------------
__global__ void rbf_prep(const int* __restrict__ i_task) {
    __shared__ int cnt[TT];
    __shared__ int base[TT];
    __shared__ int cur[TT];
    const int tid = threadIdx.x;

    if (tid < TT) { cnt[tid] = 0; cur[tid] = 0; }
    for (int idx = tid; idx < MAXG * TR; idx += blockDim.x) g_perm[idx] = -1;
    __syncthreads();

    for (int r = tid; r < NN; r += blockDim.x) atomicAdd(&cnt[i_task[r]], 1);
    __syncthreads();

    if (tid == 0) {
        int off = 0, g = 0;
        for (int t = 0; t < TT; t++) {
            base[t] = off;
            int ng = (cnt[t] + TR - 1) / TR;
            for (int k = 0; k < ng; k++) g_gtask[g++] = t;
            off += ng * TR;
        }
        for (; g < MAXG; g++) g_gtask[g] = -1;
    }
    __syncthreads();

    for (int r = tid; r < NN; r += blockDim.x) {
        int t = i_task[r];
        int p = atomicAdd(&cur[t], 1);
        g_perm[base[t] + p] = r;
    }
}

// ---------------------------------------------------------------------------
// Main: one CTA = 32 rows (same task t) x 128 columns.
// Compute phase: warp lanes = rows, warp w owns 16 columns. ii[c]==t is
// warp-uniform -> exp/FMA work only on matching columns (~1/8).
// Write phase: smem transpose-staging -> coalesced 512B row-segment STG.128.
// ---------------------------------------------------------------------------
__global__ __launch_bounds__(256) void rbf_main(
    const float* __restrict__ x,
    const float* __restrict__ xx,
    const float* __restrict__ scale_raw,
    const float* __restrict__ var_raw,
    const int*  __restrict__ ii,
    float* __restrict__ out)
{
    const int g = blockIdx.y;
    const int t = g_gtask[g];
    if (t < 0) return;                       // unused group: no rows, nothing to write

    const int c0  = blockIdx.x * TC;
    const int tid = threadIdx.x;
    const int lane = tid & 31;
    const int w    = tid >> 5;

    __shared__ float s_xx[TC * DIMC];        // 4 KB
    __shared__ int   s_ii[TC];
    __shared__ int   s_rows[TR];
    __shared__ float tile[TR * TILE_STRIDE]; // 16.5 KB, padded

    if (tid < TC) s_ii[tid] = ii[c0 + tid];
    if (tid < TR) s_rows[tid] = g_perm[g * TR + tid];
    for (int idx = tid; idx < TC * DIMC; idx += 256) s_xx[idx] = xx[c0 * DIMC + idx];

    // Per-block constants: on a match ji==jj==t, so only the diagonal entries
    // of scale/variance matter. Fold -0.5 and 1/s^2 together.
    float inv2[DIMC];
#pragma unroll
    for (int d = 0; d < DIMC; d++) {
        float s = softplus_f(scale_raw[t * (TT * DIMC) + t * DIMC + d]);
        inv2[d] = -0.5f / (s * s);
    }
    const float v = softplus_f(var_raw[t * TT + t]);

    __syncthreads();

    const int  myrow = s_rows[lane];
    const bool valid = (myrow >= 0);
    float xr[DIMC];
#pragma unroll
    for (int d = 0; d < DIMC; d++) xr[d] = 0.0f;
    if (valid) {
        const float4 a = *(const float4*)&x[myrow * DIMC + 0];
        const float4 b = *(const float4*)&x[myrow * DIMC + 4];
        xr[0] = a.x; xr[1] = a.y; xr[2] = a.z; xr[3] = a.w;
        xr[4] = b.x; xr[5] = b.y; xr[6] = b.z; xr[7] = b.w;
    }

    // ---- compute phase: warp w -> columns [w*16, w*16+16), lanes = rows ----
#pragma unroll
    for (int q = 0; q < 4; q++) {
        const int cb = w * 16 + q * 4;
        float vr[4];
#pragma unroll
        for (int k = 0; k < 4; k++) {
            const int c = cb + k;
            float val = 0.0f;
            if (s_ii[c] == t) {              // warp-uniform branch
                float sum = 0.0f;
#pragma unroll
                for (int d = 0; d < DIMC; d++) {
                    const float diff = xr[d] - s_xx[c * DIMC + d];
                    sum = fmaf(diff * diff, inv2[d], sum);
                }
                val = valid ? (__expf(sum) * v) : 0.0f;
            }
            vr[k] = val;
        }
        // STS.128: first-word bank = (4*lane + cb) % 32 -> conflict-free
        *(float4*)&tile[lane * TILE_STRIDE + cb] = make_float4(vr[0], vr[1], vr[2], vr[3]);
    }

    __syncthreads();

    // ---- write phase: warp w writes rows 4w..4w+3, coalesced 512B each ----
#pragma unroll
    for (int rr = 0; rr < 4; rr++) {
        const int r = w * 4 + rr;
        const int row = s_rows[r];
        if (row >= 0) {
            // LDS.128: banks (4r + 4*lane) % 32 -> conflict-free
            const float4 vv = *(const float4*)&tile[r * TILE_STRIDE + lane * 4];
            *(float4*)&out[(long)row * MM + c0 + lane * 4] = vv;
        }
    }
}

// ---------------------------------------------------------------------------
extern "C" void kernel_launch(void* const* d_in, const int* in_sizes, int n_in,
                              void* d_out, int out_size)
{
    const float* x     = (const float*)d_in[0];
    const float* xx    = (const float*)d_in[1];
    const float* scale = (const float*)d_in[2];
    const float* var   = (const float*)d_in[3];
    const int*   i_t   = (const int*)d_in[4];
    const int*   ii_t  = (const int*)d_in[5];
    float* out = (float*)d_out;

    rbf_prep<<<1, 256>>>(i_t);

    dim3 grid(MM / TC, MAXG);
    rbf_main<<<grid, 256>>>(x, xx, scale, var, ii_t, out);
}

// round 2
// speedup vs baseline: 1.2358x; 1.2358x over previous
#include <cuda_runtime.h>
#include <cuda_bf16.h>
#include <cstdint>

// Problem shape (fixed by the dataset): N=M=4096, DIM=8, TASKS=8
constexpr int NN   = 4096;
constexpr int MM   = 4096;
constexpr int DIMC = 8;
constexpr int TT   = 8;

constexpr int TR = 32;    // rows per group (== warp size)
constexpr int TC = 128;   // columns per tile
constexpr int TILE_STRIDE = 132;            // padded smem stride
constexpr int MAXG = 136;                   // >= floor(4096/32) + (TASKS-1) = 135

// Scratch (no cudaMalloc allowed)
__device__ int   g_perm[MAXG * TR];   // row indices grouped by task, -1 = pad
__device__ int   g_gtask[MAXG];       // task id per group, -1 = unused group
__device__ float g_inv2[TT * DIMC];   // -0.5*log2(e)/softplus(scale[t,t,d])^2
__device__ float g_v[TT];             // softplus(variance[t,t])

__device__ __forceinline__ float softplus_f(float a) {
    return (a > 20.0f) ? a : log1pf(__expf(a));
}

// ---------------------------------------------------------------------------
// Prep (1 CTA): counting-sort rows by task into 32-row groups + precompute
// all softplus-derived constants once (was redundantly done per-thread).
// ---------------------------------------------------------------------------
__global__ void rbf_prep(const int* __restrict__ i_task,
                         const float* __restrict__ scale_raw,
                         const float* __restrict__ var_raw) {
    __shared__ int cnt[TT];
    __shared__ int base[TT];
    __shared__ int cur[TT];
    const int tid = threadIdx.x;

    if (tid < TT) { cnt[tid] = 0; cur[tid] = 0; }
    for (int idx = tid; idx < MAXG * TR; idx += blockDim.x) g_perm[idx] = -1;

    // Precomputed constants: only diagonal (t,t) entries matter.
    if (tid < TT * DIMC) {
        const int t = tid / DIMC, d = tid % DIMC;
        const float s = softplus_f(scale_raw[t * (TT * DIMC) + t * DIMC + d]);
        g_inv2[tid] = -0.5f * 1.4426950408889634f / (s * s);  // fold log2(e)
    }
    if (tid < TT) g_v[tid] = softplus_f(var_raw[tid * TT + tid]);
    __syncthreads();

    for (int r = tid; r < NN; r += blockDim.x) atomicAdd(&cnt[i_task[r]], 1);
    __syncthreads();

    if (tid == 0) {
        int off = 0, g = 0;
        for (int t = 0; t < TT; t++) {
            base[t] = off;
            const int ng = (cnt[t] + TR - 1) / TR;
            for (int k = 0; k < ng; k++) g_gtask[g++] = t;
            off += ng * TR;
        }
        for (; g < MAXG; g++) g_gtask[g] = -1;
    }
    __syncthreads();

    for (int r = tid; r < NN; r += blockDim.x) {
        const int t = i_task[r];
        const int p = atomicAdd(&cur[t], 1);
        g_perm[base[t] + p] = r;
    }
}

// ---------------------------------------------------------------------------
// Main: one CTA = 32 rows (same task t) x 128 columns.
//  1. zero smem tile with STS.128
//  2. one ballot -> 16-bit warp-uniform column-match mask; __ffs loop over
//     only matched columns (~2/16), lanes = rows, xx is an LDS broadcast
//  3. coalesced 512B row-segment STG.128 out of the tile
// ---------------------------------------------------------------------------
__global__ __launch_bounds__(256) void rbf_main(
    const float* __restrict__ x,
    const float* __restrict__ xx,
    const int*  __restrict__ ii,
    float* __restrict__ out)
{
    const int g = blockIdx.y;
    const int t = g_gtask[g];
    if (t < 0) return;

    const int c0   = blockIdx.x * TC;
    const int tid  = threadIdx.x;
    const int lane = tid & 31;
    const int w    = tid >> 5;

    __shared__ float s_xx[TC * DIMC];        // 4 KB
    __shared__ int   s_ii[TC];
    __shared__ int   s_rows[TR];
    __shared__ float tile[TR * TILE_STRIDE]; // 16.5 KB

    if (tid < TC) s_ii[tid] = ii[c0 + tid];
    if (tid < TR) s_rows[tid] = g_perm[g * TR + tid];
    // xx tile: 1024 floats, one float4 per thread
    ((float4*)s_xx)[tid] = ((const float4*)(xx + c0 * DIMC))[tid];

    // zero-fill tile: 4224 floats = 1056 float4
    const float4 z4 = make_float4(0.f, 0.f, 0.f, 0.f);
#pragma unroll
    for (int idx = tid; idx < TR * TILE_STRIDE / 4; idx += 256)
        ((float4*)tile)[idx] = z4;

    // per-task constants (precomputed by prep)
    float inv2[DIMC];
    {
        const float4 a = *(const float4*)&g_inv2[t * DIMC + 0];
        const float4 b = *(const float4*)&g_inv2[t * DIMC + 4];
        inv2[0] = a.x; inv2[1] = a.y; inv2[2] = a.z; inv2[3] = a.w;
        inv2[4] = b.x; inv2[5] = b.y; inv2[6] = b.z; inv2[7] = b.w;
    }
    const float v = g_v[t];

    __syncthreads();

    const int  myrow = s_rows[lane];
    const bool valid = (myrow >= 0);
    float xr[DIMC];
#pragma unroll
    for (int d = 0; d < DIMC; d++) xr[d] = 0.0f;
    if (valid) {
        const float4 a = *(const float4*)&x[myrow * DIMC + 0];
        const float4 b = *(const float4*)&x[myrow * DIMC + 4];
        xr[0] = a.x; xr[1] = a.y; xr[2] = a.z; xr[3] = a.w;
        xr[4] = b.x; xr[5] = b.y; xr[6] = b.z; xr[7] = b.w;
    }

    // warp-uniform 16-bit match mask for this warp's 16 columns
    const int cchk = w * 16 + (lane & 15);
    unsigned mask = __ballot_sync(0xffffffffu, (s_ii[cchk] == t) && (lane < 16));

    while (mask) {
        const int k = __ffs(mask) - 1;
        mask &= mask - 1;
        const int c = w * 16 + k;
        const float4 xa = *(const float4*)&s_xx[c * DIMC + 0];  // broadcast
        const float4 xb = *(const float4*)&s_xx[c * DIMC + 4];
        float sum;
        float d0 = xr[0] - xa.x; sum  = d0 * d0 * inv2[0];
        float d1 = xr[1] - xa.y; sum  = fmaf(d1 * d1, inv2[1], sum);
        float d2 = xr[2] - xa.z; sum  = fmaf(d2 * d2, inv2[2], sum);
        float d3 = xr[3] - xa.w; sum  = fmaf(d3 * d3, inv2[3], sum);
        float d4 = xr[4] - xb.x; sum  = fmaf(d4 * d4, inv2[4], sum);
        float d5 = xr[5] - xb.y; sum  = fmaf(d5 * d5, inv2[5], sum);
        float d6 = xr[6] - xb.z; sum  = fmaf(d6 * d6, inv2[6], sum);
        float d7 = xr[7] - xb.w; sum  = fmaf(d7 * d7, inv2[7], sum);
        const float val = exp2f(sum) * v;   // log2e folded into inv2
        if (valid) tile[lane * TILE_STRIDE + c] = val;
    }

    __syncthreads();

    // write phase: warp w writes rows 4w..4w+3, 512B coalesced each
#pragma unroll
    for (int rr = 0; rr < 4; rr++) {
        const int r = w * 4 + rr;
        const int row = s_rows[r];
        if (row >= 0) {
            const float4 vv = *(const float4*)&tile[r * TILE_STRIDE + lane * 4];
            *(float4*)&out[(long)row * MM + c0 + lane * 4] = vv;
        }
    }
}

// ---------------------------------------------------------------------------
extern "C" void kernel_launch(void* const* d_in, const int* in_sizes, int n_in,
                              void* d_out, int out_size)
{
    const float* x     = (const float*)d_in[0];
    const float* xx    = (const float*)d_in[1];
    const float* scale = (const float*)d_in[2];
    const float* var   = (const float*)d_in[3];
    const int*   i_t   = (const int*)d_in[4];
    const int*   ii_t  = (const int*)d_in[5];
    float* out = (float*)d_out;

    rbf_prep<<<1, 256>>>(i_t, scale, var);

    dim3 grid(MM / TC, MAXG);
    rbf_main<<<grid, 256>>>(x, xx, ii_t, out);
}